// round 1
// baseline (speedup 1.0000x reference)
#include <cuda_runtime.h>
#include <math.h>

#define NB 4
#define ND 128
#define NT 4096
#define NK 64
#define NV 128

// Scratch (static device globals — no allocation in kernel_launch).
__device__ float g_W[256 * 128];          // rows: [0:64)=Wq, [64:128)=Wk, [128:256)=Wv
__device__ float g_bias[256];
__device__ float g_QKV[NB * NT * 256];    // per row: [Q(64) | K(64) | V(128)]
__device__ float g_colsum[NB * NT];
__device__ float g_Vs[NB * NT * NV];      // V scaled by 1/(8*colsum[t])

// ---------------------------------------------------------------------------
// Kernel 0: pack weights/bias into one matrix, zero colsum accumulators.
// 16384 threads.
__global__ void prep_kernel(const float* __restrict__ Wk, const float* __restrict__ bk,
                            const float* __restrict__ Wq, const float* __restrict__ bq,
                            const float* __restrict__ Wv, const float* __restrict__ bv) {
    int i = blockIdx.x * blockDim.x + threadIdx.x;   // [0, 16384)
    if (i < 64 * 128) {
        g_W[i] = Wq[i];
        g_W[64 * 128 + i] = Wk[i];
    }
    g_W[128 * 128 + i] = Wv[i];   // i covers full 128*128
    if (i < 64) { g_bias[i] = bq[i]; g_bias[64 + i] = bk[i]; }
    if (i < 128) g_bias[128 + i] = bv[i];
    if (i < NB * NT) g_colsum[i] = 0.0f;
}

// ---------------------------------------------------------------------------
// Kernel 1: QKV projection.  QKV[m][n] = sum_d x[m][d] * g_W[n][d] + bias[n]
// x[m=(b,t)][d] = minibatch[b][d][t]  (transposed read, coalesced over t).
// Block tile 64x64, Ktile=32, 256 threads, 4x4 micro-tile per thread.
__global__ void qkv_kernel(const float* __restrict__ mb) {
    int n0 = blockIdx.x * 64;           // output column tile (0..192)
    int m0 = blockIdx.y * 64;           // global row
    int b  = m0 >> 12;
    int t0 = m0 & (NT - 1);
    const float* x = mb + (size_t)b * ND * NT;   // [d][t]

    __shared__ float Xs[64][33];
    __shared__ float Ws[64][33];

    int tid = threadIdx.x;
    int tx = tid & 15, ty = tid >> 4;
    float acc[4][4] = {};

    for (int k0 = 0; k0 < 128; k0 += 32) {
        // Xs[r][kk] = x[(k0+kk)*NT + t0 + r]   (coalesced over r)
        {
            int r = tid & 63, kkb = tid >> 6;   // kkb 0..3
#pragma unroll
            for (int i = 0; i < 8; i++) {
                int kk = kkb + i * 4;
                Xs[r][kk] = x[(k0 + kk) * NT + t0 + r];
            }
        }
        // Ws[nn][kk] = g_W[(n0+nn)*128 + k0 + kk]  (coalesced over kk)
        {
            int kk = tid & 31, nnb = tid >> 5;  // nnb 0..7
#pragma unroll
            for (int i = 0; i < 8; i++) {
                int nn = nnb + i * 8;
                Ws[nn][kk] = g_W[(n0 + nn) * 128 + k0 + kk];
            }
        }
        __syncthreads();
#pragma unroll
        for (int k = 0; k < 32; k++) {
            float xv[4], wv[4];
#pragma unroll
            for (int i = 0; i < 4; i++) xv[i] = Xs[ty * 4 + i][k];
#pragma unroll
            for (int j = 0; j < 4; j++) wv[j] = Ws[tx * 4 + j][k];
#pragma unroll
            for (int i = 0; i < 4; i++)
#pragma unroll
                for (int j = 0; j < 4; j++) acc[i][j] += xv[i] * wv[j];
        }
        __syncthreads();
    }
#pragma unroll
    for (int i = 0; i < 4; i++) {
        int r = ty * 4 + i;
        float* dst = g_QKV + (size_t)(m0 + r) * 256;
#pragma unroll
        for (int j = 0; j < 4; j++) {
            int n = n0 + tx * 4 + j;
            dst[n] = acc[i][j] + g_bias[n];
        }
    }
}

// ---------------------------------------------------------------------------
// Kernel 2: colsum[b][t] = sum_{q >= t} exp(Q[q] . K[t])
// grid: (t-tile 64, b 4, q-chunk 8 of 512 rows). fp32 atomics for cross-chunk sum.
__global__ void colsum_kernel() {
    const int QCHUNK = 512;
    int t0 = blockIdx.x * 64;
    int b  = blockIdx.y;
    int qlo = blockIdx.z * QCHUNK;
    if (qlo + QCHUNK - 1 < t0) return;   // no valid q >= t0 in this chunk

    __shared__ float Ks[64][65];
    __shared__ float Qs[64][65];
    __shared__ float cs[64];

    const float* qkv = g_QKV + (size_t)b * NT * 256;
    int tid = threadIdx.x;

    {   // K tile
        int k = tid & 63, tb = tid >> 6;
#pragma unroll
        for (int i = 0; i < 16; i++) {
            int tt = tb + i * 4;
            Ks[tt][k] = qkv[(t0 + tt) * 256 + 64 + k];
        }
    }
    if (tid < 64) cs[tid] = 0.0f;
    __syncthreads();

    int tx = tid & 15, ty = tid >> 4;
    float local[4] = {};

    for (int q0 = qlo; q0 < qlo + QCHUNK; q0 += 64) {
        if (q0 + 63 < t0) continue;      // block-uniform skip
        {   // Q tile
            int k = tid & 63, qb = tid >> 6;
#pragma unroll
            for (int i = 0; i < 16; i++) {
                int qq = qb + i * 4;
                Qs[qq][k] = qkv[(q0 + qq) * 256 + k];
            }
        }
        __syncthreads();
        float s[4][4] = {};
#pragma unroll
        for (int k = 0; k < 64; k++) {
            float qv[4], kv[4];
#pragma unroll
            for (int i = 0; i < 4; i++) qv[i] = Qs[ty * 4 + i][k];
#pragma unroll
            for (int j = 0; j < 4; j++) kv[j] = Ks[tx * 4 + j][k];
#pragma unroll
            for (int i = 0; i < 4; i++)
#pragma unroll
                for (int j = 0; j < 4; j++) s[i][j] += qv[i] * kv[j];
        }
#pragma unroll
        for (int i = 0; i < 4; i++)
#pragma unroll
            for (int j = 0; j < 4; j++) {
                int qg = q0 + ty * 4 + i, tg = t0 + tx * 4 + j;
                if (qg >= tg) local[j] += __expf(s[i][j]);
            }
        __syncthreads();
    }
#pragma unroll
    for (int j = 0; j < 4; j++) atomicAdd(&cs[tx * 4 + j], local[j]);
    __syncthreads();
    if (tid < 64) atomicAdd(&g_colsum[b * NT + t0 + tid], cs[tid]);
}

// ---------------------------------------------------------------------------
// Kernel 3: g_Vs[b][t][v] = V[b][t][v] / (8 * colsum[b][t])
__global__ void scalev_kernel() {
    int idx = blockIdx.x * 256 + threadIdx.x;   // [0, 4*4096*128)
    int t = (idx >> 7) & (NT - 1);
    int b = idx >> 19;
    int v = idx & 127;
    float inv = 1.0f / (8.0f * g_colsum[b * NT + t]);
    g_Vs[idx] = g_QKV[(((size_t)b * NT + t) << 8) + 128 + v] * inv;
}

// ---------------------------------------------------------------------------
// Kernel 4: read[q,:] = sum_{t<=q} exp(Q[q].K[t]) * Vs[t,:],  out = transpose(x + read)
// Block = one 64-row q tile; loops over t tiles <= q tile (recompute S).
// Dynamic smem: Qs(64x65) Ks(64x65) Es(64x65) Vss(64x132, reused as output stage)
__global__ void attn_kernel(const float* __restrict__ mb, float* __restrict__ out) {
    extern __shared__ float sm[];
    float* Qs  = sm;
    float* Ks  = Qs + 64 * 65;
    float* Es  = Ks + 64 * 65;
    float* Vss = Es + 64 * 65;

    int xx = blockIdx.x;
    int qt = (xx & 1) ? (63 - (xx >> 1)) : (xx >> 1);   // interleave long/short blocks
    int b = blockIdx.y;
    int q0 = qt * 64;
    const float* qkv = g_QKV + (size_t)b * NT * 256;
    int tid = threadIdx.x;

    {   // Q tile (persistent)
        int k = tid & 63, qb = tid >> 6;
#pragma unroll
        for (int i = 0; i < 16; i++) {
            int qq = qb + i * 4;
            Qs[qq * 65 + k] = qkv[(q0 + qq) * 256 + k];
        }
    }

    int tx = tid & 15, ty = tid >> 4;   // stage A layout (16x16, 4x4 tiles)
    int vx = tid & 31, wy = tid >> 5;   // stage B: warp wy -> q rows wy*8..+7, cols vx*4..+3
    float acc[8][4] = {};

    for (int tt = 0; tt <= qt; tt++) {
        int t0 = tt * 64;
        {   // K tile
            int k = tid & 63, tb = tid >> 6;
#pragma unroll
            for (int i = 0; i < 16; i++) {
                int t_ = tb + i * 4;
                Ks[t_ * 65 + k] = qkv[(t0 + t_) * 256 + 64 + k];
            }
        }
        {   // Vs tile, float4 coalesced
            const float4* src = (const float4*)(g_Vs + ((size_t)b * NT + t0) * NV);
            int v4 = tid & 31, tb = tid >> 5;
#pragma unroll
            for (int i = 0; i < 8; i++) {
                int t_ = tb + i * 8;
                float4 val = src[t_ * 32 + v4];
                *(float4*)(Vss + t_ * 132 + v4 * 4) = val;
            }
        }
        __syncthreads();

        // stage A: Es = exp(Q Ks^T) with causal mask
        {
            float s[4][4] = {};
#pragma unroll
            for (int k = 0; k < 64; k++) {
                float qv[4], kv[4];
#pragma unroll
                for (int i = 0; i < 4; i++) qv[i] = Qs[(ty * 4 + i) * 65 + k];
#pragma unroll
                for (int j = 0; j < 4; j++) kv[j] = Ks[(tx * 4 + j) * 65 + k];
#pragma unroll
                for (int i = 0; i < 4; i++)
#pragma unroll
                    for (int j = 0; j < 4; j++) s[i][j] += qv[i] * kv[j];
            }
#pragma unroll
            for (int i = 0; i < 4; i++)
#pragma unroll
                for (int j = 0; j < 4; j++) {
                    int qg = q0 + ty * 4 + i, tg = t0 + tx * 4 + j;
                    Es[(ty * 4 + i) * 65 + tx * 4 + j] = (tg <= qg) ? __expf(s[i][j]) : 0.0f;
                }
        }
        __syncthreads();

        // stage B: acc += Es @ Vss
#pragma unroll 4
        for (int t_ = 0; t_ < 64; t_++) {
            float4 vv = *(const float4*)(Vss + t_ * 132 + vx * 4);
#pragma unroll
            for (int i = 0; i < 8; i++) {
                float e = Es[(wy * 8 + i) * 65 + t_];
                acc[i][0] += e * vv.x;
                acc[i][1] += e * vv.y;
                acc[i][2] += e * vv.z;
                acc[i][3] += e * vv.w;
            }
        }
        __syncthreads();
    }

    // stage acc -> smem so final [d][t] writes are coalesced over t
    float* stage = Vss;   // 64 rows x 128 cols, stride 132
#pragma unroll
    for (int i = 0; i < 8; i++) {
        *(float4*)(stage + (wy * 8 + i) * 132 + vx * 4) =
            make_float4(acc[i][0], acc[i][1], acc[i][2], acc[i][3]);
    }
    __syncthreads();
    {
        int qq = tid & 63, db = tid >> 6;
        const float* xin = mb + (size_t)b * ND * NT;
        float* o = out + (size_t)b * ND * NT;
#pragma unroll
        for (int i = 0; i < 32; i++) {
            int d = db + i * 4;
            o[d * NT + q0 + qq] = xin[d * NT + q0 + qq] + stage[qq * 132 + d];
        }
    }
}

// ---------------------------------------------------------------------------
#define ATT_SMEM ((64 * 65 * 3 + 64 * 132) * 4)   // 83712 bytes

extern "C" void kernel_launch(void* const* d_in, const int* in_sizes, int n_in,
                              void* d_out, int out_size) {
    const float* mb = (const float*)d_in[0];
    const float* Wk = (const float*)d_in[1];
    const float* bk = (const float*)d_in[2];
    const float* Wq = (const float*)d_in[3];
    const float* bq = (const float*)d_in[4];
    const float* Wv = (const float*)d_in[5];
    const float* bv = (const float*)d_in[6];
    float* out = (float*)d_out;

    cudaFuncSetAttribute(attn_kernel, cudaFuncAttributeMaxDynamicSharedMemorySize, ATT_SMEM);

    prep_kernel<<<64, 256>>>(Wk, bk, Wq, bq, Wv, bv);
    qkv_kernel<<<dim3(4, 256), 256>>>(mb);
    colsum_kernel<<<dim3(64, 4, 8), 256>>>();
    scalev_kernel<<<(NB * NT * NV) / 256, 256>>>();
    attn_kernel<<<dim3(64, 4), 256, ATT_SMEM>>>(mb, out);
}

// round 2
// speedup vs baseline: 3.4174x; 3.4174x over previous
#include <cuda_runtime.h>
#include <math.h>

#define NB 4
#define ND 128
#define NT 4096
#define NK 64
#define NV 128

// Scratch (static device globals — no allocation in kernel_launch).
__device__ float g_W[256 * 128];          // rows: [0:64)=Wq, [64:128)=Wk, [128:256)=Wv
__device__ float g_bias[256];
__device__ float g_QKV[NB * NT * 256];    // per row: [Q(64) | K(64) | V(128)]
__device__ float g_colsum[NB * NT];
__device__ float g_Vs[NB * NT * NV];      // V scaled by 1/(8*colsum[t])

// ---------------------------------------------------------------------------
// m16n8k8 tf32 mma (row.col). Operands are fp32 bit patterns (HW truncates).
__device__ __forceinline__ void mma8(float* d, const unsigned* a, const unsigned* b) {
    asm volatile(
        "mma.sync.aligned.m16n8k8.row.col.f32.tf32.tf32.f32 "
        "{%0,%1,%2,%3}, {%4,%5,%6,%7}, {%8,%9}, {%0,%1,%2,%3};\n"
        : "+f"(d[0]), "+f"(d[1]), "+f"(d[2]), "+f"(d[3])
        : "r"(a[0]), "r"(a[1]), "r"(a[2]), "r"(a[3]), "r"(b[0]), "r"(b[1]));
}

// ---------------------------------------------------------------------------
// Kernel 0: pack weights/bias into one matrix, zero colsum accumulators.
__global__ void prep_kernel(const float* __restrict__ Wk, const float* __restrict__ bk,
                            const float* __restrict__ Wq, const float* __restrict__ bq,
                            const float* __restrict__ Wv, const float* __restrict__ bv) {
    int i = blockIdx.x * blockDim.x + threadIdx.x;   // [0, 16384)
    if (i < 64 * 128) {
        g_W[i] = Wq[i];
        g_W[64 * 128 + i] = Wk[i];
    }
    g_W[128 * 128 + i] = Wv[i];
    if (i < 64) { g_bias[i] = bq[i]; g_bias[64 + i] = bk[i]; }
    if (i < 128) g_bias[128 + i] = bv[i];
    if (i < NB * NT) g_colsum[i] = 0.0f;
}

// ---------------------------------------------------------------------------
// Kernel 1: QKV projection (fp32, small: ~1 GFLOP).
__global__ void qkv_kernel(const float* __restrict__ mb) {
    int n0 = blockIdx.x * 64;
    int m0 = blockIdx.y * 64;
    int b  = m0 >> 12;
    int t0 = m0 & (NT - 1);
    const float* x = mb + (size_t)b * ND * NT;

    __shared__ float Xs[64][33];
    __shared__ float Ws[64][33];

    int tid = threadIdx.x;
    int tx = tid & 15, ty = tid >> 4;
    float acc[4][4] = {};

    for (int k0 = 0; k0 < 128; k0 += 32) {
        {
            int r = tid & 63, kkb = tid >> 6;
#pragma unroll
            for (int i = 0; i < 8; i++) {
                int kk = kkb + i * 4;
                Xs[r][kk] = x[(k0 + kk) * NT + t0 + r];
            }
        }
        {
            int kk = tid & 31, nnb = tid >> 5;
#pragma unroll
            for (int i = 0; i < 8; i++) {
                int nn = nnb + i * 8;
                Ws[nn][kk] = g_W[(n0 + nn) * 128 + k0 + kk];
            }
        }
        __syncthreads();
#pragma unroll
        for (int k = 0; k < 32; k++) {
            float xv[4], wv[4];
#pragma unroll
            for (int i = 0; i < 4; i++) xv[i] = Xs[ty * 4 + i][k];
#pragma unroll
            for (int j = 0; j < 4; j++) wv[j] = Ws[tx * 4 + j][k];
#pragma unroll
            for (int i = 0; i < 4; i++)
#pragma unroll
                for (int j = 0; j < 4; j++) acc[i][j] += xv[i] * wv[j];
        }
        __syncthreads();
    }
#pragma unroll
    for (int i = 0; i < 4; i++) {
        int r = ty * 4 + i;
        float* dst = g_QKV + (size_t)(m0 + r) * 256;
#pragma unroll
        for (int j = 0; j < 4; j++) {
            int n = n0 + tx * 4 + j;
            dst[n] = acc[i][j] + g_bias[n];
        }
    }
}

// ---------------------------------------------------------------------------
// Kernel 2: colsum[b][t] = sum_{q >= t} exp(Q[q].K[t])  — tf32 mma version.
// grid: (t-tile 64, b 4, q-chunk 8 of 512 rows). 256 threads = 8 warps.
// Warp layout over 64x64 S tile: wr = w&1 (32 q-rows), wc = w>>1 (16 t-cols).
__global__ void colsum_kernel() {
    const int QCHUNK = 512;
    int t0 = blockIdx.x * 64;
    int b  = blockIdx.y;
    int qlo = blockIdx.z * QCHUNK;
    if (qlo + QCHUNK - 1 < t0) return;

    __shared__ float Ks[64 * 68];
    __shared__ float Qs[64 * 68];
    __shared__ float cs[64];

    const float* qkv = g_QKV + (size_t)b * NT * 256;
    int tid = threadIdx.x;
    int lane = tid & 31, w = tid >> 5;
    int g = lane >> 2, tg = lane & 3;
    int wr = w & 1, wc = w >> 1;

    {   // K tile, float4 coalesced
        int f4 = tid & 15, r0 = tid >> 4;
#pragma unroll
        for (int i = 0; i < 4; i++) {
            int r = r0 + 16 * i;
            *(float4*)&Ks[r * 68 + f4 * 4] = *(const float4*)&qkv[(t0 + r) * 256 + 64 + f4 * 4];
        }
    }
    if (tid < 64) cs[tid] = 0.0f;
    __syncthreads();

    // Hoist K (B-operand) fragments: tile fixed for the whole block.
    unsigned bf[2][8][2];
#pragma unroll
    for (int ni = 0; ni < 2; ni++)
#pragma unroll
        for (int kk = 0; kk < 8; kk++) {
            int trow = wc * 16 + ni * 8 + g;
            bf[ni][kk][0] = __float_as_uint(Ks[trow * 68 + kk * 8 + tg]);
            bf[ni][kk][1] = __float_as_uint(Ks[trow * 68 + kk * 8 + tg + 4]);
        }

    float colacc[2][2] = {};

    for (int q0 = qlo; q0 < qlo + QCHUNK; q0 += 64) {
        if (q0 + 63 < t0) continue;   // block-uniform skip
        __syncthreads();
        {   // Q tile
            int f4 = tid & 15, r0 = tid >> 4;
#pragma unroll
            for (int i = 0; i < 4; i++) {
                int r = r0 + 16 * i;
                *(float4*)&Qs[r * 68 + f4 * 4] = *(const float4*)&qkv[(q0 + r) * 256 + f4 * 4];
            }
        }
        __syncthreads();

        float d[2][2][4] = {};
#pragma unroll
        for (int kk = 0; kk < 8; kk++) {
            unsigned a[2][4];
#pragma unroll
            for (int mi = 0; mi < 2; mi++) {
                int r = wr * 32 + mi * 16;
                a[mi][0] = __float_as_uint(Qs[(r + g) * 68 + kk * 8 + tg]);
                a[mi][1] = __float_as_uint(Qs[(r + g + 8) * 68 + kk * 8 + tg]);
                a[mi][2] = __float_as_uint(Qs[(r + g) * 68 + kk * 8 + tg + 4]);
                a[mi][3] = __float_as_uint(Qs[(r + g + 8) * 68 + kk * 8 + tg + 4]);
            }
#pragma unroll
            for (int mi = 0; mi < 2; mi++)
#pragma unroll
                for (int ni = 0; ni < 2; ni++)
                    mma8(d[mi][ni], a[mi], bf[ni][kk]);
        }
        // mask + exp + per-thread column accumulate
#pragma unroll
        for (int mi = 0; mi < 2; mi++)
#pragma unroll
            for (int ni = 0; ni < 2; ni++)
#pragma unroll
                for (int e = 0; e < 4; e++) {
                    int row = q0 + wr * 32 + mi * 16 + g + (e >> 1) * 8;
                    int col = t0 + wc * 16 + ni * 8 + 2 * tg + (e & 1);
                    if (row >= col) colacc[ni][e & 1] += __expf(d[mi][ni][e]);
                }
    }

    // reduce over g (lanes differing in bits 2..4), then atomics
#pragma unroll
    for (int ni = 0; ni < 2; ni++)
#pragma unroll
        for (int j = 0; j < 2; j++) {
            float v = colacc[ni][j];
            v += __shfl_xor_sync(0xffffffffu, v, 4);
            v += __shfl_xor_sync(0xffffffffu, v, 8);
            v += __shfl_xor_sync(0xffffffffu, v, 16);
            colacc[ni][j] = v;
        }
    if (g == 0) {
#pragma unroll
        for (int ni = 0; ni < 2; ni++) {
            atomicAdd(&cs[wc * 16 + ni * 8 + 2 * tg], colacc[ni][0]);
            atomicAdd(&cs[wc * 16 + ni * 8 + 2 * tg + 1], colacc[ni][1]);
        }
    }
    __syncthreads();
    if (tid < 64) atomicAdd(&g_colsum[b * NT + t0 + tid], cs[tid]);
}

// ---------------------------------------------------------------------------
// Kernel 3: g_Vs[b][t][v] = V[b][t][v] / (8 * colsum[b][t])
__global__ void scalev_kernel() {
    int idx = blockIdx.x * 256 + threadIdx.x;
    int t = (idx >> 7) & (NT - 1);
    int b = idx >> 19;
    int v = idx & 127;
    float inv = 1.0f / (8.0f * g_colsum[b * NT + t]);
    g_Vs[idx] = g_QKV[(((size_t)b * NT + t) << 8) + 128 + v] * inv;
}

// ---------------------------------------------------------------------------
// Kernel 4: read[q,:] = sum_{t<=q} exp(Q[q].K[t]) * Vs[t,:], out = (x+read)^T
// tf32 mma for both S and E@V. 256 threads, Q fragments hoisted.
__global__ void attn_kernel(const float* __restrict__ mb, float* __restrict__ out) {
    extern __shared__ float sm[];
    float* Qs  = sm;              // 64*68
    float* Ks  = Qs + 64 * 68;    // 64*68
    float* Es  = Ks + 64 * 68;    // 64*68
    float* Vss = Es + 64 * 68;    // 64*136 (reused as output stage)

    int xx = blockIdx.x;
    int qt = (xx & 1) ? (63 - (xx >> 1)) : (xx >> 1);   // interleave long/short
    int b = blockIdx.y;
    int q0 = qt * 64;
    const float* qkv = g_QKV + (size_t)b * NT * 256;
    int tid = threadIdx.x;
    int lane = tid & 31, w = tid >> 5;
    int g = lane >> 2, tg = lane & 3;
    int wr = w & 1, wc = w >> 1;

    {   // Q tile (persistent)
        int f4 = tid & 15, r0 = tid >> 4;
#pragma unroll
        for (int i = 0; i < 4; i++) {
            int r = r0 + 16 * i;
            *(float4*)&Qs[r * 68 + f4 * 4] = *(const float4*)&qkv[(q0 + r) * 256 + f4 * 4];
        }
    }
    __syncthreads();

    // Hoist Q (A-operand) fragments: fixed across the whole t-loop.
    unsigned qa[2][8][4];
#pragma unroll
    for (int mi = 0; mi < 2; mi++)
#pragma unroll
        for (int kk = 0; kk < 8; kk++) {
            int r = wr * 32 + mi * 16;
            qa[mi][kk][0] = __float_as_uint(Qs[(r + g) * 68 + kk * 8 + tg]);
            qa[mi][kk][1] = __float_as_uint(Qs[(r + g + 8) * 68 + kk * 8 + tg]);
            qa[mi][kk][2] = __float_as_uint(Qs[(r + g) * 68 + kk * 8 + tg + 4]);
            qa[mi][kk][3] = __float_as_uint(Qs[(r + g + 8) * 68 + kk * 8 + tg + 4]);
        }

    float acc[2][4][4] = {};   // EV accumulator: rows wr*32+mi*16+{g,g+8}, cols wc*32+ni*8+2tg+{0,1}

    for (int tt = 0; tt <= qt; tt++) {
        int t0 = tt * 64;
        __syncthreads();    // protect Ks/Vss/Es from previous iteration's readers
        {   // K tile
            int f4 = tid & 15, r0 = tid >> 4;
#pragma unroll
            for (int i = 0; i < 4; i++) {
                int r = r0 + 16 * i;
                *(float4*)&Ks[r * 68 + f4 * 4] = *(const float4*)&qkv[(t0 + r) * 256 + 64 + f4 * 4];
            }
        }
        {   // Vs tile
            const float4* src = (const float4*)(g_Vs + ((size_t)b * NT + t0) * NV);
            int v4 = tid & 31, r0 = tid >> 5;
#pragma unroll
            for (int i = 0; i < 8; i++) {
                int r = r0 + 8 * i;
                *(float4*)&Vss[r * 136 + v4 * 4] = src[r * 32 + v4];
            }
        }
        __syncthreads();

        // Stage A: S = Q K^T  ->  Es = exp(masked S)
        {
            float d[2][2][4] = {};
#pragma unroll
            for (int kk = 0; kk < 8; kk++) {
                unsigned bfr[2][2];
#pragma unroll
                for (int ni = 0; ni < 2; ni++) {
                    int trow = wc * 16 + ni * 8 + g;
                    bfr[ni][0] = __float_as_uint(Ks[trow * 68 + kk * 8 + tg]);
                    bfr[ni][1] = __float_as_uint(Ks[trow * 68 + kk * 8 + tg + 4]);
                }
#pragma unroll
                for (int mi = 0; mi < 2; mi++)
#pragma unroll
                    for (int ni = 0; ni < 2; ni++)
                        mma8(d[mi][ni], qa[mi][kk], bfr[ni]);
            }
            bool diag = (tt == qt);
#pragma unroll
            for (int mi = 0; mi < 2; mi++)
#pragma unroll
                for (int ni = 0; ni < 2; ni++)
#pragma unroll
                    for (int e2 = 0; e2 < 2; e2++) {
                        int rloc = wr * 32 + mi * 16 + g + e2 * 8;
                        int cloc = wc * 16 + ni * 8 + 2 * tg;
                        float v0 = __expf(d[mi][ni][e2 * 2 + 0]);
                        float v1 = __expf(d[mi][ni][e2 * 2 + 1]);
                        if (diag) {
                            if (cloc > rloc) v0 = 0.0f;
                            if (cloc + 1 > rloc) v1 = 0.0f;
                        }
                        *(float2*)&Es[rloc * 68 + cloc] = make_float2(v0, v1);
                    }
        }
        __syncthreads();

        // Stage B: acc += Es @ Vss
#pragma unroll
        for (int kk = 0; kk < 8; kk++) {
            unsigned a[2][4], bfr[4][2];
#pragma unroll
            for (int mi = 0; mi < 2; mi++) {
                int r = wr * 32 + mi * 16;
                a[mi][0] = __float_as_uint(Es[(r + g) * 68 + kk * 8 + tg]);
                a[mi][1] = __float_as_uint(Es[(r + g + 8) * 68 + kk * 8 + tg]);
                a[mi][2] = __float_as_uint(Es[(r + g) * 68 + kk * 8 + tg + 4]);
                a[mi][3] = __float_as_uint(Es[(r + g + 8) * 68 + kk * 8 + tg + 4]);
            }
#pragma unroll
            for (int ni = 0; ni < 4; ni++) {
                int vcol = wc * 32 + ni * 8 + g;
                bfr[ni][0] = __float_as_uint(Vss[(kk * 8 + tg) * 136 + vcol]);
                bfr[ni][1] = __float_as_uint(Vss[(kk * 8 + tg + 4) * 136 + vcol]);
            }
#pragma unroll
            for (int mi = 0; mi < 2; mi++)
#pragma unroll
                for (int ni = 0; ni < 4; ni++)
                    mma8(acc[mi][ni], a[mi], bfr[ni]);
        }
    }

    __syncthreads();
    // Stage accumulator into smem (reuse Vss) so final [d][t] writes coalesce over t.
#pragma unroll
    for (int mi = 0; mi < 2; mi++)
#pragma unroll
        for (int ni = 0; ni < 4; ni++)
#pragma unroll
            for (int e2 = 0; e2 < 2; e2++) {
                int rloc = wr * 32 + mi * 16 + g + e2 * 8;
                int cloc = wc * 32 + ni * 8 + 2 * tg;
                *(float2*)&Vss[rloc * 136 + cloc] =
                    make_float2(acc[mi][ni][e2 * 2], acc[mi][ni][e2 * 2 + 1]);
            }
    __syncthreads();
    {
        int qq = tid & 63, db = tid >> 6;
        const float* xin = mb + (size_t)b * ND * NT;
        float* o = out + (size_t)b * ND * NT;
#pragma unroll
        for (int i = 0; i < 32; i++) {
            int d_ = db + i * 4;
            o[d_ * NT + q0 + qq] = xin[d_ * NT + q0 + qq] + Vss[qq * 136 + d_];
        }
    }
}

// ---------------------------------------------------------------------------
#define ATT_SMEM ((64 * 68 * 3 + 64 * 136) * 4)   // 87040 bytes

extern "C" void kernel_launch(void* const* d_in, const int* in_sizes, int n_in,
                              void* d_out, int out_size) {
    const float* mb = (const float*)d_in[0];
    const float* Wk = (const float*)d_in[1];
    const float* bk = (const float*)d_in[2];
    const float* Wq = (const float*)d_in[3];
    const float* bq = (const float*)d_in[4];
    const float* Wv = (const float*)d_in[5];
    const float* bv = (const float*)d_in[6];
    float* out = (float*)d_out;

    cudaFuncSetAttribute(attn_kernel, cudaFuncAttributeMaxDynamicSharedMemorySize, ATT_SMEM);

    prep_kernel<<<64, 256>>>(Wk, bk, Wq, bq, Wv, bv);
    qkv_kernel<<<dim3(4, 256), 256>>>(mb);
    colsum_kernel<<<dim3(64, 4, 8), 256>>>();
    scalev_kernel<<<(NB * NT * NV) / 256, 256>>>();
    attn_kernel<<<dim3(64, 4), 256, ATT_SMEM>>>(mb, out);
}